// round 2
// baseline (speedup 1.0000x reference)
#include <cuda_runtime.h>
#include <math.h>

#define Bc 2
#define Tc 2048
#define Dc 1024
#define Lc 8
#define FFc 2048
#define Vc 50257
#define Mc (Bc*Tc)   // 4096 rows

typedef unsigned long long u64;
typedef unsigned int u32;

// packed fp32x2 FMA (Blackwell; ptxas never emits this from C++ — PTX only)
#define FMA_F32X2(d, a, b, c) \
    asm("fma.rn.f32x2 %0, %1, %2, %3;" : "=l"(d) : "l"(a), "l"(b), "l"(c))
#define PACK_DUP_F32X2(out, v) \
    asm("mov.b64 %0, {%1, %1};" : "=l"(out) : "r"(__float_as_uint(v)))

// ---------------- scratch (no allocs allowed) ----------------
__device__ float g_x[Mc * Dc];   // residual stream     16 MB
__device__ float g_n[Mc * Dc];   // rmsnorm output      16 MB
__device__ float g_p[Mc * Dc];   // pre / scan states   16 MB
__device__ float g_f[Mc * FFc];  // ff hidden           32 MB

// ---------------- embedding gather ----------------
__global__ void embed_kernel(const int* __restrict__ ids,
                             const float* __restrict__ embed,
                             float* __restrict__ x) {
    int m = blockIdx.x;            // row 0..4095
    int t = threadIdx.x;           // 0..255, one float4 each (D/4 = 256)
    const float4* src = (const float4*)(embed + (long)ids[m] * Dc);
    ((float4*)(x + (long)m * Dc))[t] = src[t];
}

// ---------------- rmsnorm ----------------
__global__ void rmsnorm_kernel(const float* __restrict__ in,
                               const float* __restrict__ w,
                               float* __restrict__ out) {
    int m = blockIdx.x;
    int t = threadIdx.x;  // 256 threads, 1 float4 each
    float4 v = ((const float4*)(in + (long)m * Dc))[t];
    float ss = v.x * v.x + v.y * v.y + v.z * v.z + v.w * v.w;
    __shared__ float red[8];
    #pragma unroll
    for (int o = 16; o > 0; o >>= 1) ss += __shfl_xor_sync(0xffffffffu, ss, o);
    if ((t & 31) == 0) red[t >> 5] = ss;
    __syncthreads();
    if (t < 32) {
        float s2 = (t < 8) ? red[t] : 0.0f;
        #pragma unroll
        for (int o = 4; o > 0; o >>= 1) s2 += __shfl_xor_sync(0xffffffffu, s2, o);
        if (t == 0) red[0] = s2;
    }
    __syncthreads();
    float rs = rsqrtf(red[0] * (1.0f / Dc) + 1e-6f);
    float4 wv = ((const float4*)w)[t];
    float4 o4;
    o4.x = v.x * rs * wv.x;
    o4.y = v.y * rs * wv.y;
    o4.z = v.z * rs * wv.z;
    o4.w = v.w * rs * wv.w;
    ((float4*)(out + (long)m * Dc))[t] = o4;
}

// ---------------- diagonal tanh scan (in-place on pre) ----------------
__global__ void scan_kernel(float* __restrict__ pre,
                            const float* __restrict__ a_diag) {
    int tid = blockIdx.x * blockDim.x + threadIdx.x;   // 0..2047
    int b = tid / Dc;
    int d = tid % Dc;
    float a = a_diag[d];
    float s = 0.0f;
    float* p = pre + (long)b * Tc * Dc + d;
    float nxt = *p;
    for (int t = 0; t < Tc; t++) {
        float cur = nxt;
        if (t + 1 < Tc) nxt = p[Dc];          // prefetch off the serial chain
        s = tanhf(fmaf(a, s, cur));
        *p = s;
        p += Dc;
    }
}

// ---------------- SGEMM (fp32, packed f32x2 FMA, reg-prefetch pipeline) ----
// C[M,N] (+)= A[M,K] * B + bias, optional SiLU.
// BTRANS=false: B is [K,N] row-major.   BTRANS=true: B is [N,K] row-major.
// 128x128x16 tiles, 256 threads, 8x8 micro-tile (as 8x4 f32x2 pairs).
template <bool BTRANS, int ACT, bool ACCUM, bool NBOUND>
__global__ __launch_bounds__(256, 2)
void gemm_kernel(const float* __restrict__ A, const float* __restrict__ B,
                 const float* __restrict__ bias, float* __restrict__ C,
                 int M, int N, int K) {
    __shared__ float As[16][128];
    __shared__ float Bs[16][128];

    int tid = threadIdx.x;
    int tx = tid & 15;   // col group
    int ty = tid >> 4;   // row group
    int bn = blockIdx.x * 128;
    int bm = blockIdx.y * 128;

    // load-index precompute
    const int a_r = tid >> 2;          // 0..63 (i=0), +64 (i=1)
    const int a_c = (tid & 3) * 4;
    const int b_r = tid >> 5;          // 0..7 (i=0), +8 (i=1)   [!BTRANS]
    const int b_c = (tid & 31) * 4;

    u64 acc[8][4];
    #pragma unroll
    for (int i = 0; i < 8; i++)
        #pragma unroll
        for (int j = 0; j < 4; j++) acc[i][j] = 0ull;

    float4 pa0, pa1, pb0, pb1;

    auto load_tiles = [&](int k0) {
        pa0 = *(const float4*)(A + (long)(bm + a_r) * K + k0 + a_c);
        pa1 = *(const float4*)(A + (long)(bm + 64 + a_r) * K + k0 + a_c);
        if (!BTRANS) {
            pb0 = *(const float4*)(B + (long)(k0 + b_r) * N + bn + b_c);
            pb1 = *(const float4*)(B + (long)(k0 + 8 + b_r) * N + bn + b_c);
        } else {
            pb0 = make_float4(0.f, 0.f, 0.f, 0.f);
            pb1 = make_float4(0.f, 0.f, 0.f, 0.f);
            if (!NBOUND || (bn + a_r) < N)
                pb0 = *(const float4*)(B + (long)(bn + a_r) * K + k0 + a_c);
            if (!NBOUND || (bn + 64 + a_r) < N)
                pb1 = *(const float4*)(B + (long)(bn + 64 + a_r) * K + k0 + a_c);
        }
    };
    auto store_tiles = [&]() {
        As[a_c + 0][a_r] = pa0.x; As[a_c + 1][a_r] = pa0.y;
        As[a_c + 2][a_r] = pa0.z; As[a_c + 3][a_r] = pa0.w;
        As[a_c + 0][64 + a_r] = pa1.x; As[a_c + 1][64 + a_r] = pa1.y;
        As[a_c + 2][64 + a_r] = pa1.z; As[a_c + 3][64 + a_r] = pa1.w;
        if (!BTRANS) {
            *(float4*)&Bs[b_r][b_c] = pb0;
            *(float4*)&Bs[8 + b_r][b_c] = pb1;
        } else {
            Bs[a_c + 0][a_r] = pb0.x; Bs[a_c + 1][a_r] = pb0.y;
            Bs[a_c + 2][a_r] = pb0.z; Bs[a_c + 3][a_r] = pb0.w;
            Bs[a_c + 0][64 + a_r] = pb1.x; Bs[a_c + 1][64 + a_r] = pb1.y;
            Bs[a_c + 2][64 + a_r] = pb1.z; Bs[a_c + 3][64 + a_r] = pb1.w;
        }
    };

    load_tiles(0);
    store_tiles();
    __syncthreads();

    for (int k0 = 0; k0 < K; k0 += 16) {
        bool more = (k0 + 16) < K;
        if (more) load_tiles(k0 + 16);   // issue global loads, consume post-sync

        #pragma unroll
        for (int kk = 0; kk < 16; kk++) {
            float4 a0 = *(float4*)&As[kk][ty * 4];
            float4 a1 = *(float4*)&As[kk][64 + ty * 4];
            float4 b0 = *(float4*)&Bs[kk][tx * 4];
            float4 b1 = *(float4*)&Bs[kk][64 + tx * 4];
            u64 bp[4];
            bp[0] = ((u64*)&b0)[0]; bp[1] = ((u64*)&b0)[1];
            bp[2] = ((u64*)&b1)[0]; bp[3] = ((u64*)&b1)[1];
            float ar[8] = {a0.x, a0.y, a0.z, a0.w, a1.x, a1.y, a1.z, a1.w};
            #pragma unroll
            for (int i = 0; i < 8; i++) {
                u64 ap;
                PACK_DUP_F32X2(ap, ar[i]);
                #pragma unroll
                for (int j = 0; j < 4; j++)
                    FMA_F32X2(acc[i][j], ap, bp[j], acc[i][j]);
            }
        }
        __syncthreads();
        if (more) {
            store_tiles();
            __syncthreads();
        }
    }

    // epilogue: unpack f32x2 accumulators
    #pragma unroll
    for (int gi = 0; gi < 2; gi++) {
        #pragma unroll
        for (int ii = 0; ii < 4; ii++) {
            int row = bm + gi * 64 + ty * 4 + ii;
            #pragma unroll
            for (int gj = 0; gj < 2; gj++) {
                #pragma unroll
                for (int jp = 0; jp < 2; jp++) {
                    u64 v = acc[gi * 4 + ii][gj * 2 + jp];
                    int col0 = bn + gj * 64 + tx * 4 + jp * 2;
                    float vals[2] = {__uint_as_float((u32)v),
                                     __uint_as_float((u32)(v >> 32))};
                    #pragma unroll
                    for (int h = 0; h < 2; h++) {
                        int col = col0 + h;
                        if (NBOUND && col >= N) continue;
                        float c = vals[h];
                        if (bias) c += bias[col];
                        if (ACT == 1) c = c / (1.0f + expf(-c));  // silu
                        long idx = (long)row * N + col;
                        if (ACCUM) C[idx] += c; else C[idx] = c;
                    }
                }
            }
        }
    }
}

// ---------------- driver ----------------
extern "C" void kernel_launch(void* const* d_in, const int* in_sizes, int n_in,
                              void* d_out, int out_size) {
    const int*   ids    = (const int*)d_in[0];
    const float* embed  = (const float*)d_in[1];
    const float* norm1  = (const float*)d_in[2];
    const float* norm2  = (const float*)d_in[3];
    const float* adiag  = (const float*)d_in[4];
    const float* W_in   = (const float*)d_in[5];
    const float* b_in   = (const float*)d_in[6];
    const float* W_out  = (const float*)d_in[7];
    const float* ff_w1  = (const float*)d_in[8];
    const float* ff_b1  = (const float*)d_in[9];
    const float* ff_w2  = (const float*)d_in[10];
    const float* ff_b2  = (const float*)d_in[11];
    const float* fnorm  = (const float*)d_in[12];
    const float* lm     = (const float*)d_in[13];
    float* out = (float*)d_out;

    float *x, *nb, *p, *f;
    cudaGetSymbolAddress((void**)&x,  g_x);
    cudaGetSymbolAddress((void**)&nb, g_n);
    cudaGetSymbolAddress((void**)&p,  g_p);
    cudaGetSymbolAddress((void**)&f,  g_f);

    embed_kernel<<<Mc, 256>>>(ids, embed, x);

    dim3 gD(Dc / 128, Mc / 128);     // N=1024 gemms: 8x32
    dim3 gF(FFc / 128, Mc / 128);    // N=2048 gemm: 16x32

    for (int l = 0; l < Lc; l++) {
        rmsnorm_kernel<<<Mc, 256>>>(x, norm1 + l * Dc, nb);
        gemm_kernel<false, 0, false, false><<<gD, 256>>>(
            nb, W_in + (long)l * Dc * Dc, b_in + l * Dc, p, Mc, Dc, Dc);
        scan_kernel<<<8, 256>>>(p, adiag + l * Dc);
        gemm_kernel<false, 0, true, false><<<gD, 256>>>(
            p, W_out + (long)l * Dc * Dc, (const float*)nullptr, x, Mc, Dc, Dc);
        rmsnorm_kernel<<<Mc, 256>>>(x, norm2 + l * Dc, nb);
        gemm_kernel<false, 1, false, false><<<gF, 256>>>(
            nb, ff_w1 + (long)l * Dc * FFc, ff_b1 + l * FFc, f, Mc, FFc, Dc);
        gemm_kernel<false, 0, true, false><<<gD, 256>>>(
            f, ff_w2 + (long)l * FFc * Dc, ff_b2 + l * Dc, x, Mc, Dc, FFc);
    }

    rmsnorm_kernel<<<Mc, 256>>>(x, fnorm, nb);
    dim3 gV((Vc + 127) / 128, Mc / 128);   // 393 x 32
    gemm_kernel<true, 0, false, true><<<gV, 256>>>(
        nb, lm, (const float*)nullptr, out, Mc, Vc, Dc);
}

// round 5
// speedup vs baseline: 2.0060x; 2.0060x over previous
#include <cuda_runtime.h>
#include <cuda_bf16.h>
#include <math.h>

#define Bc 2
#define Tc 2048
#define Dc 1024
#define Lc 8
#define FFc 2048
#define Vc 50257
#define Mc (Bc*Tc)   // 4096 rows

typedef unsigned long long u64;
typedef unsigned int u32;
typedef unsigned short u16;

// ================= base-ISA tensor-core primitives (sm_80+, safe on sm_103) ===
__device__ __forceinline__ u32 smem_u32(const void* p) {
    u32 a;
    asm("{ .reg .u64 t; cvta.to.shared.u64 t, %1; cvt.u32.u64 %0, t; }" : "=r"(a) : "l"(p));
    return a;
}
__device__ __forceinline__ void ldmat4(u32& r0, u32& r1, u32& r2, u32& r3, u32 addr) {
    asm volatile("ldmatrix.sync.aligned.m8n8.x4.shared.b16 {%0,%1,%2,%3}, [%4];"
                 : "=r"(r0), "=r"(r1), "=r"(r2), "=r"(r3) : "r"(addr));
}
__device__ __forceinline__ void mma16816(float* d, const u32* a, u32 b0, u32 b1) {
    asm volatile("mma.sync.aligned.m16n8k16.row.col.f32.bf16.bf16.f32 "
                 "{%0,%1,%2,%3}, {%4,%5,%6,%7}, {%8,%9}, {%0,%1,%2,%3};"
                 : "+f"(d[0]), "+f"(d[1]), "+f"(d[2]), "+f"(d[3])
                 : "r"(a[0]), "r"(a[1]), "r"(a[2]), "r"(a[3]), "r"(b0), "r"(b1));
}
__device__ __forceinline__ void cpasync16(u32 saddr, const void* gaddr, int srcsize) {
    asm volatile("cp.async.cg.shared.global [%0], [%1], 16, %2;"
                 :: "r"(saddr), "l"(gaddr), "r"(srcsize) : "memory");
}
#define CP_COMMIT() asm volatile("cp.async.commit_group;" ::: "memory")
#define CP_WAIT(n)  asm volatile("cp.async.wait_group %0;" :: "n"(n) : "memory")

// ================= scratch (device globals; no allocs) ========================
__device__ float g_x[Mc * Dc];   // residual stream fp32
__device__ float g_p[Mc * Dc];   // W_in output (scan input) fp32
// activation hi/lo bf16
__device__ u16 g_ah[Mc * Dc],  g_al[Mc * Dc];
__device__ u16 g_fh[Mc * FFc], g_fl[Mc * FFc];
// weights: [N,K] K-major bf16 hi/lo
__device__ u16 g_win_h[Lc * Dc * Dc],  g_win_l[Lc * Dc * Dc];
__device__ u16 g_wout_h[Lc * Dc * Dc], g_wout_l[Lc * Dc * Dc];
__device__ u16 g_ff1_h[Lc * Dc * FFc], g_ff1_l[Lc * Dc * FFc];
__device__ u16 g_ff2_h[Lc * FFc * Dc], g_ff2_l[Lc * FFc * Dc];
__device__ u16 g_lm_h[(long)Vc * Dc],  g_lm_l[(long)Vc * Dc];

// ================= helpers =================
__device__ __forceinline__ u32 pk2u(u16 a, u16 b) { return (u32)a | ((u32)b << 16); }
__device__ __forceinline__ void cvt_hilo(float x, u16& h, u16& l) {
    __nv_bfloat16 hb = __float2bfloat16_rn(x);
    __nv_bfloat16 lb = __float2bfloat16_rn(x - __bfloat162float(hb));
    h = __bfloat16_as_ushort(hb);
    l = __bfloat16_as_ushort(lb);
}

// ================= embedding =================
__global__ void embed_kernel(const int* __restrict__ ids, const float* __restrict__ embed,
                             float* __restrict__ x) {
    int m = blockIdx.x;
    int t = threadIdx.x;
    ((float4*)(x + (long)m * Dc))[t] = ((const float4*)(embed + (long)ids[m] * Dc))[t];
}

// ================= rmsnorm -> bf16 hi/lo =================
__global__ void rmsnorm_hilo(const float* __restrict__ in, const float* __restrict__ w,
                             u16* __restrict__ oh, u16* __restrict__ ol) {
    int m = blockIdx.x;
    int t = threadIdx.x;  // 256
    float4 v = ((const float4*)(in + (long)m * Dc))[t];
    float ss = v.x * v.x + v.y * v.y + v.z * v.z + v.w * v.w;
    __shared__ float red[8];
    #pragma unroll
    for (int o = 16; o > 0; o >>= 1) ss += __shfl_xor_sync(0xffffffffu, ss, o);
    if ((t & 31) == 0) red[t >> 5] = ss;
    __syncthreads();
    if (t < 32) {
        float s2 = (t < 8) ? red[t] : 0.0f;
        #pragma unroll
        for (int o = 4; o > 0; o >>= 1) s2 += __shfl_xor_sync(0xffffffffu, s2, o);
        if (t == 0) red[0] = s2;
    }
    __syncthreads();
    float rs = rsqrtf(red[0] * (1.0f / Dc) + 1e-6f);
    float4 wv = ((const float4*)w)[t];
    float o0 = v.x * rs * wv.x, o1 = v.y * rs * wv.y, o2 = v.z * rs * wv.z, o3 = v.w * rs * wv.w;
    u16 h0,l0,h1,l1,h2,l2,h3,l3;
    cvt_hilo(o0,h0,l0); cvt_hilo(o1,h1,l1); cvt_hilo(o2,h2,l2); cvt_hilo(o3,h3,l3);
    long base = (long)m * Dc + t * 4;
    *(uint2*)(oh + base) = make_uint2(pk2u(h0,h1), pk2u(h2,h3));
    *(uint2*)(ol + base) = make_uint2(pk2u(l0,l1), pk2u(l2,l3));
}

// ================= scan: tanh SSM, writes states as bf16 hi/lo =================
__global__ void scan_kernel(const float* __restrict__ pre, const float* __restrict__ a_diag,
                            u16* __restrict__ oh, u16* __restrict__ ol) {
    int tid = blockIdx.x * 32 + threadIdx.x;   // 0..2047
    int b = tid >> 10;
    int d = tid & 1023;
    float a = a_diag[d];
    float s = 0.0f;
    const float* p = pre + (long)b * Tc * Dc + d;
    u16* ph = oh + (long)b * Tc * Dc + d;
    u16* pl = ol + (long)b * Tc * Dc + d;
    float nxt = *p;
    for (int t = 0; t < Tc; t++) {
        float cur = nxt;
        if (t + 1 < Tc) nxt = p[Dc];
        float xx = fmaf(a, s, cur);
        float ax = fabsf(xx);
        float e = __expf(-2.0f * ax);
        float r = __fdividef(1.0f - e, 1.0f + e);
        s = copysignf(r, xx);
        u16 h, l; cvt_hilo(s, h, l);
        *ph = h; *pl = l;
        p += Dc; ph += Dc; pl += Dc;
    }
}

// ================= weight transpose + hi/lo: in[K,N] -> out[N,K] ==============
__global__ void transcvt_kernel(const float* __restrict__ in,
                                u16* __restrict__ oh, u16* __restrict__ ol, int K, int N) {
    __shared__ float tile[32][33];
    long off = (long)blockIdx.z * K * N;
    in += off; oh += off; ol += off;
    int n0 = blockIdx.x * 32, k0 = blockIdx.y * 32;
    int tx = threadIdx.x, ty = threadIdx.y;   // 32 x 8
    #pragma unroll
    for (int j = 0; j < 4; j++)
        tile[ty + j * 8][tx] = in[(long)(k0 + ty + j * 8) * N + n0 + tx];
    __syncthreads();
    #pragma unroll
    for (int j = 0; j < 4; j++) {
        int n = n0 + ty + j * 8, k = k0 + tx;
        u16 h, l; cvt_hilo(tile[tx][ty + j * 8], h, l);
        oh[(long)n * K + k] = h;
        ol[(long)n * K + k] = l;
    }
}

// ================= elementwise hi/lo convert (lm_head already [N,K]) ==========
__global__ void cvt_kernel(const float* __restrict__ in, u16* __restrict__ oh,
                           u16* __restrict__ ol, long n) {
    long i = ((long)blockIdx.x * blockDim.x + threadIdx.x) * 4;
    if (i >= n) return;
    float4 v = *(const float4*)(in + i);
    u16 h0,l0,h1,l1,h2,l2,h3,l3;
    cvt_hilo(v.x,h0,l0); cvt_hilo(v.y,h1,l1); cvt_hilo(v.z,h2,l2); cvt_hilo(v.w,h3,l3);
    *(uint2*)(oh + i) = make_uint2(pk2u(h0,h1), pk2u(h2,h3));
    *(uint2*)(ol + i) = make_uint2(pk2u(l0,l1), pk2u(l2,l3));
}

// ================= HMMA GEMM ==================================================
// C[M,N] (+)= (Ah+Al)[M,K] * (Bh+Bl)^T + bias  (3-term Ootomo, fp32 accum)
// A,B bf16 hi/lo, both [rows, K] K-major. 128x128 tile, k-chunk 32,
// 256 threads = 8 warps (4x2), warp tile 32x64, cp.async double buffer.
#define STG 32768           // stage size: 4 tiles x 8KB
#define T_AH 0
#define T_AL 8192
#define T_BH 16384
#define T_BL 24576

__device__ __forceinline__ u32 tile_off(int row, int chunk) {
    return (u32)(row * 64 + ((chunk ^ ((row >> 1) & 3)) << 4));
}

template <int ACT, bool ACCUM, bool NBOUND, bool OUTHILO>
__global__ __launch_bounds__(256)
void gemm_mma(const u16* __restrict__ Ah, const u16* __restrict__ Al,
              const u16* __restrict__ Bh, const u16* __restrict__ Bl,
              const float* __restrict__ bias, float* __restrict__ C,
              u16* __restrict__ Ch, u16* __restrict__ Cl,
              int M, int N, int K) {
    extern __shared__ char sm[];
    const u32 sbase = smem_u32(sm);
    const int t = threadIdx.x;
    const int lane = t & 31;
    const int wid = t >> 5;
    const int wm = wid & 3;          // 4 m-groups of 32 rows
    const int wn = wid >> 2;         // 2 n-groups of 64 cols
    const int bn = blockIdx.x * 128;
    const int bm = blockIdx.y * 128;

    float d[2][8][4];
    #pragma unroll
    for (int i = 0; i < 2; i++)
        #pragma unroll
        for (int j = 0; j < 8; j++)
            #pragma unroll
            for (int k = 0; k < 4; k++) d[i][j][k] = 0.0f;

    const int KT = K >> 5;

    // per-thread copy descriptors: 8 chunks of 16B (2048 chunks / 256 threads)
    auto copy_stage = [&](int stage, int k0) {
        u32 sdst = sbase + stage * STG;
        #pragma unroll
        for (int i = 0; i < 8; i++) {
            int g = i * 256 + t;
            int tile = g >> 9;            // 0:Ah 1:Al 2:Bh 3:Bl
            int row = (g >> 2) & 127;
            int c = g & 3;
            u32 so = sdst + tile * 8192 + tile_off(row, c);
            const u16* base = (tile == 0) ? Ah : (tile == 1) ? Al : (tile == 2) ? Bh : Bl;
            int grow = (tile < 2) ? (bm + row) : (bn + row);
            int srcsize = 16;
            if (NBOUND && tile >= 2 && grow >= N) { grow = N - 1; srcsize = 0; }
            cpasync16(so, base + (long)grow * K + k0 + c * 8, srcsize);
        }
    };

    copy_stage(0, 0);
    CP_COMMIT();

    for (int kt = 0; kt < KT; kt++) {
        int s = kt & 1;
        if (kt + 1 < KT) {
            copy_stage(1 - s, (kt + 1) << 5);
            CP_COMMIT();
            CP_WAIT(1);
        } else {
            CP_WAIT(0);
        }
        __syncthreads();

        u32 sb = sbase + s * STG;
        const int lrow = lane & 15;
        const int lsel = lane >> 4;
        #pragma unroll
        for (int ks = 0; ks < 2; ks++) {
            int chunk = ks * 2 + lsel;
            u32 ah[2][4], al[2][4];
            #pragma unroll
            for (int ma = 0; ma < 2; ma++) {
                int r = wm * 32 + ma * 16 + lrow;
                ldmat4(ah[ma][0], ah[ma][1], ah[ma][2], ah[ma][3], sb + T_AH + tile_off(r, chunk));
                ldmat4(al[ma][0], al[ma][1], al[ma][2], al[ma][3], sb + T_AL + tile_off(r, chunk));
            }
            u32 bh[4][4], bl[4][4];
            #pragma unroll
            for (int g = 0; g < 4; g++) {
                int r = wn * 64 + g * 16 + lrow;
                ldmat4(bh[g][0], bh[g][1], bh[g][2], bh[g][3], sb + T_BH + tile_off(r, chunk));
                ldmat4(bl[g][0], bl[g][1], bl[g][2], bl[g][3], sb + T_BL + tile_off(r, chunk));
            }
            #pragma unroll
            for (int ma = 0; ma < 2; ma++) {
                #pragma unroll
                for (int j = 0; j < 8; j++) {
                    int g = j >> 1;
                    u32 h0 = (j & 1) ? bh[g][1] : bh[g][0];
                    u32 h1 = (j & 1) ? bh[g][3] : bh[g][2];
                    u32 l0 = (j & 1) ? bl[g][1] : bl[g][0];
                    u32 l1 = (j & 1) ? bl[g][3] : bl[g][2];
                    mma16816(d[ma][j], ah[ma], h0, h1);   // Ah*Bh
                    mma16816(d[ma][j], ah[ma], l0, l1);   // Ah*Bl
                    mma16816(d[ma][j], al[ma], h0, h1);   // Al*Bh
                }
            }
        }
        __syncthreads();
    }

    // ---------------- epilogue ----------------
    #pragma unroll
    for (int ma = 0; ma < 2; ma++) {
        int row0 = bm + wm * 32 + ma * 16 + (lane >> 2);
        #pragma unroll
        for (int j = 0; j < 8; j++) {
            int col = bn + wn * 64 + j * 8 + 2 * (lane & 3);
            #pragma unroll
            for (int half = 0; half < 2; half++) {   // c0c1 row0 ; c2c3 row0+8
                int row = row0 + half * 8;
                float v0 = d[ma][j][half * 2 + 0];
                float v1 = d[ma][j][half * 2 + 1];
                if (bias) { v0 += __ldg(bias + col); v1 += __ldg(bias + col + 1); }
                if (ACT == 1) {
                    v0 = v0 / (1.0f + __expf(-v0));
                    v1 = v1 / (1.0f + __expf(-v1));
                }
                long idx = (long)row * N + col;
                if (OUTHILO) {
                    u16 h0,l0,h1,l1;
                    cvt_hilo(v0,h0,l0); cvt_hilo(v1,h1,l1);
                    *(u32*)(Ch + idx) = pk2u(h0,h1);
                    *(u32*)(Cl + idx) = pk2u(l0,l1);
                } else if (!NBOUND) {
                    if (ACCUM) {
                        float2 old = *(float2*)(C + idx);
                        v0 += old.x; v1 += old.y;
                    }
                    *(float2*)(C + idx) = make_float2(v0, v1);
                } else {
                    if (col < N)     C[idx]     = v0;
                    if (col + 1 < N) C[idx + 1] = v1;
                }
            }
        }
    }
}

// ================= driver =================
extern "C" void kernel_launch(void* const* d_in, const int* in_sizes, int n_in,
                              void* d_out, int out_size) {
    const int*   ids    = (const int*)d_in[0];
    const float* embed  = (const float*)d_in[1];
    const float* norm1  = (const float*)d_in[2];
    const float* norm2  = (const float*)d_in[3];
    const float* adiag  = (const float*)d_in[4];
    const float* W_in   = (const float*)d_in[5];
    const float* b_in   = (const float*)d_in[6];
    const float* W_out  = (const float*)d_in[7];
    const float* ff_w1  = (const float*)d_in[8];
    const float* ff_b1  = (const float*)d_in[9];
    const float* ff_w2  = (const float*)d_in[10];
    const float* ff_b2  = (const float*)d_in[11];
    const float* fnorm  = (const float*)d_in[12];
    const float* lm     = (const float*)d_in[13];
    float* out = (float*)d_out;

    float *x, *p;
    cudaGetSymbolAddress((void**)&x, g_x);
    cudaGetSymbolAddress((void**)&p, g_p);
    u16 *ah, *al, *fh, *fl;
    cudaGetSymbolAddress((void**)&ah, g_ah); cudaGetSymbolAddress((void**)&al, g_al);
    cudaGetSymbolAddress((void**)&fh, g_fh); cudaGetSymbolAddress((void**)&fl, g_fl);
    u16 *winh, *winl, *wouth, *woutl, *ff1h, *ff1l, *ff2h, *ff2l, *lmh, *lml;
    cudaGetSymbolAddress((void**)&winh,  g_win_h);  cudaGetSymbolAddress((void**)&winl,  g_win_l);
    cudaGetSymbolAddress((void**)&wouth, g_wout_h); cudaGetSymbolAddress((void**)&woutl, g_wout_l);
    cudaGetSymbolAddress((void**)&ff1h,  g_ff1_h);  cudaGetSymbolAddress((void**)&ff1l,  g_ff1_l);
    cudaGetSymbolAddress((void**)&ff2h,  g_ff2_h);  cudaGetSymbolAddress((void**)&ff2l,  g_ff2_l);
    cudaGetSymbolAddress((void**)&lmh,   g_lm_h);   cudaGetSymbolAddress((void**)&lml,   g_lm_l);

    const int SMSZ = 2 * STG;   // 64 KB dynamic
    cudaFuncSetAttribute(gemm_mma<0,false,false,false>, cudaFuncAttributeMaxDynamicSharedMemorySize, SMSZ);
    cudaFuncSetAttribute(gemm_mma<0,true ,false,false>, cudaFuncAttributeMaxDynamicSharedMemorySize, SMSZ);
    cudaFuncSetAttribute(gemm_mma<1,false,false,true >, cudaFuncAttributeMaxDynamicSharedMemorySize, SMSZ);
    cudaFuncSetAttribute(gemm_mma<0,false,true ,false>, cudaFuncAttributeMaxDynamicSharedMemorySize, SMSZ);

    // weight prep (every launch; deterministic)
    transcvt_kernel<<<dim3(Dc/32,  Dc/32,  Lc), dim3(32,8)>>>(W_in,  winh,  winl,  Dc,  Dc);
    transcvt_kernel<<<dim3(Dc/32,  Dc/32,  Lc), dim3(32,8)>>>(W_out, wouth, woutl, Dc,  Dc);
    transcvt_kernel<<<dim3(FFc/32, Dc/32,  Lc), dim3(32,8)>>>(ff_w1, ff1h,  ff1l,  Dc,  FFc);
    transcvt_kernel<<<dim3(Dc/32,  FFc/32, Lc), dim3(32,8)>>>(ff_w2, ff2h,  ff2l,  FFc, Dc);
    {
        long n = (long)Vc * Dc;
        long blocks = (n / 4 + 255) / 256;
        cvt_kernel<<<(int)blocks, 256>>>(lm, lmh, lml, n);
    }

    embed_kernel<<<Mc, 256>>>(ids, embed, x);

    dim3 gD(Dc / 128, Mc / 128);     // 8 x 32
    dim3 gF(FFc / 128, Mc / 128);    // 16 x 32

    for (int l = 0; l < Lc; l++) {
        long oD = (long)l * Dc * Dc;
        long oF = (long)l * Dc * FFc;
        rmsnorm_hilo<<<Mc, 256>>>(x, norm1 + l * Dc, ah, al);
        gemm_mma<0,false,false,false><<<gD, 256, SMSZ>>>(
            ah, al, winh + oD, winl + oD, b_in + l * Dc, p, nullptr, nullptr, Mc, Dc, Dc);
        scan_kernel<<<64, 32>>>(p, adiag + l * Dc, ah, al);
        gemm_mma<0,true,false,false><<<gD, 256, SMSZ>>>(
            ah, al, wouth + oD, woutl + oD, nullptr, x, nullptr, nullptr, Mc, Dc, Dc);
        rmsnorm_hilo<<<Mc, 256>>>(x, norm2 + l * Dc, ah, al);
        gemm_mma<1,false,false,true><<<gF, 256, SMSZ>>>(
            ah, al, ff1h + oF, ff1l + oF, ff_b1 + l * FFc, nullptr, fh, fl, Mc, FFc, Dc);
        gemm_mma<0,true,false,false><<<gD, 256, SMSZ>>>(
            fh, fl, ff2h + oF, ff2l + oF, ff_b2 + l * Dc, x, nullptr, nullptr, Mc, Dc, FFc);
    }

    rmsnorm_hilo<<<Mc, 256>>>(x, fnorm, ah, al);
    dim3 gV((Vc + 127) / 128, Mc / 128);   // 393 x 32
    gemm_mma<0,false,true,false><<<gV, 256, SMSZ>>>(
        ah, al, lmh, lml, nullptr, out, nullptr, nullptr, Mc, Vc, Dc);
}